// round 1
// baseline (speedup 1.0000x reference)
#include <cuda_runtime.h>

// Problem constants (fixed shapes from reference)
#define CCH 32
#define DD 48
#define HHH 48
#define WWW 48
#define HW (HHH*WWW)           // 2304
#define DHW (DD*HHH*WWW)       // 110592
#define TT 8
#define EPSf 1e-6f
#define THREADS 256

// packed fp32x2 helpers (sm_103a FFMA2 path)
__device__ __forceinline__ void ffma2(unsigned long long &acc, unsigned long long w, unsigned long long v) {
    asm("fma.rn.f32x2 %0, %1, %2, %0;" : "+l"(acc) : "l"(w), "l"(v));
}
__device__ __forceinline__ unsigned long long pack2(float a) {
    unsigned long long r; asm("mov.b64 %0, {%1, %1};" : "=l"(r) : "f"(a)); return r;
}
__device__ __forceinline__ float2 unpack2(unsigned long long a) {
    float2 f; asm("mov.b64 {%0, %1}, %2;" : "=f"(f.x), "=f"(f.y) : "l"(a)); return f;
}

__device__ __forceinline__ float reflectf(float t, float size) {
    float c = fabsf(t + 0.5f);
    float m = fmodf(c, 2.0f * size);
    return fminf(m, 2.0f * size - m) - 0.5f;
}

__global__ __launch_bounds__(THREADS, 2)
void geo_sample3d_kernel(const float* __restrict__ x,
                         const float* __restrict__ w_field,
                         const float* __restrict__ b_field,
                         const float* __restrict__ gates,
                         const float* __restrict__ w_mix,
                         const float* __restrict__ b_mix,
                         float* __restrict__ out,
                         int total_vox)
{
    // shared: transposed w_mix [m][o] (32 KB), field weights, biases, gate sigmoids
    __shared__ float s_wmixT[TT*CCH*CCH];   // [m*32 + o]
    __shared__ float s_wf[12*CCH];
    __shared__ float s_bf[12];
    __shared__ float s_bmix[CCH];
    __shared__ float s_sg[TT];

    const int tid = threadIdx.x;
    for (int i = tid; i < TT*CCH*CCH; i += THREADS) {
        int m = i >> 5, o = i & 31;
        s_wmixT[i] = w_mix[o * (TT*CCH) + m];
    }
    for (int i = tid; i < 12*CCH; i += THREADS) s_wf[i] = w_field[i];
    if (tid < 12)  s_bf[tid]   = b_field[tid];
    if (tid < CCH) s_bmix[tid] = b_mix[tid];
    if (tid < TT)  s_sg[tid]   = 1.0f / (1.0f + expf(-gates[tid]));
    __syncthreads();

    const int idx = blockIdx.x * THREADS + tid;
    if (idx >= total_vox) return;

    const int n   = idx / DHW;
    const int zyx = idx - n * DHW;
    const int z   = zyx / HW;
    const int r2i = zyx - z * HW;
    const int y   = r2i / WWW;
    const int w   = r2i - y * WWW;

    const float* __restrict__ xn = x + (size_t)n * CCH * DHW;

    // ---- Phase 1: field conv f[12] = w_field @ x[:, voxel] + b_field ----
    float f[12];
    #pragma unroll
    for (int o = 0; o < 12; o++) f[o] = s_bf[o];
    #pragma unroll 4
    for (int c = 0; c < CCH; c++) {
        float xc = xn[c * DHW + zyx];
        #pragma unroll
        for (int o = 0; o < 12; o++) f[o] = fmaf(s_wf[o*CCH + c], xc, f[o]);
    }

    // ---- Phase 2: per-direction geometry + folded token coefficients ----
    int   ib[6], ox[6], oy[6], oz[6];
    float fx[6], fy[6], fz[6];
    float cA[3], cG[9], cLs[3];
    float sumIr2 = 0.0f;

    const float gx0 = (w + 0.5f) * (2.0f / WWW) - 1.0f;
    const float gy0 = (y + 0.5f) * (2.0f / HHH) - 1.0f;
    const float gz0 = (z + 0.5f) * (2.0f / DD)  - 1.0f;

    #pragma unroll
    for (int k = 0; k < 3; k++) {
        float vx = f[4*k+0], vy = f[4*k+1], vz = f[4*k+2], fr = f[4*k+3];
        float inv_norm = rsqrtf(vx*vx + vy*vy + vz*vz + EPSf);
        float ux = vx * inv_norm, uy = vy * inv_norm, uz = vz * inv_norm;
        float r  = 0.5f + 1.5f / (1.0f + expf(-fr));
        float dx = 2.0f * r * ux / ((float)WWW + EPSf);
        float dy = 2.0f * r * uy / ((float)HHH + EPSf);
        float dz = 2.0f * r * uz / ((float)DD  + EPSf);
        float invr = 1.0f / (r + EPSf);
        float ir2  = invr * invr;
        sumIr2 += ir2;

        cA[k]     = 0.5f * s_sg[1+k];
        cG[0*3+k] = s_sg[4] * 0.5f * invr * ux;
        cG[1*3+k] = s_sg[5] * 0.5f * invr * uy;
        cG[2*3+k] = s_sg[6] * 0.5f * invr * uz;
        cLs[k]    = s_sg[7] * (1.0f/3.0f) * ir2;

        #pragma unroll
        for (int s2 = 0; s2 < 2; s2++) {
            float sgn = s2 ? -1.0f : 1.0f;
            int   si  = 2*k + s2;
            // unnormalize to voxel coords, then reflect-pad
            float txu = ((gx0 + sgn*dx + 1.0f) * (float)WWW - 1.0f) * 0.5f;
            float tyu = ((gy0 + sgn*dy + 1.0f) * (float)HHH - 1.0f) * 0.5f;
            float tzu = ((gz0 + sgn*dz + 1.0f) * (float)DD  - 1.0f) * 0.5f;
            float ixs = reflectf(txu, (float)WWW);
            float iys = reflectf(tyu, (float)HHH);
            float izs = reflectf(tzu, (float)DD);

            float x0f = floorf(ixs), y0f = floorf(iys), z0f = floorf(izs);
            fx[si] = ixs - x0f;  fy[si] = iys - y0f;  fz[si] = izs - z0f;

            int x0i = (int)x0f; x0i = max(0, min(x0i, WWW-1)); int x1i = min(x0i+1, WWW-1);
            int y0i = (int)y0f; y0i = max(0, min(y0i, HHH-1)); int y1i = min(y0i+1, HHH-1);
            int z0i = (int)z0f; z0i = max(0, min(z0i, DD-1));  int z1i = min(z0i+1, DD-1);

            ib[si] = z0i * HW + y0i * WWW + x0i;
            ox[si] = x1i - x0i;
            oy[si] = (y1i - y0i) * WWW;
            oz[si] = (z1i - z0i) * HW;
        }
    }

    const float cLx = -s_sg[7] * (2.0f/3.0f) * sumIr2;
    const float cx  = s_sg[0];

    // ---- Phase 3: channel loop — gather 6 trilinear samples, stream tokens into mix ----
    unsigned long long acc[16];
    #pragma unroll
    for (int j = 0; j < 16; j++) acc[j] = 0ull;

    #pragma unroll 1
    for (int c = 0; c < CCH; c++) {
        const float* __restrict__ bc = xn + c * DHW;
        float xc = bc[zyx];

        float sv[6];
        #pragma unroll
        for (int si = 0; si < 6; si++) {
            const float* p  = bc + ib[si];
            const float* pz = p + oz[si];
            float v000 = p[0],          v001 = p[ox[si]];
            float v010 = p[oy[si]],     v011 = p[oy[si] + ox[si]];
            float v100 = pz[0],         v101 = pz[ox[si]];
            float v110 = pz[oy[si]],    v111 = pz[oy[si] + ox[si]];
            float c00 = v000 + fx[si] * (v001 - v000);
            float c01 = v010 + fx[si] * (v011 - v010);
            float c10 = v100 + fx[si] * (v101 - v100);
            float c11 = v110 + fx[si] * (v111 - v110);
            float c0  = c00 + fy[si] * (c01 - c00);
            float c1  = c10 + fy[si] * (c11 - c10);
            sv[si] = c0 + fz[si] * (c1 - c0);
        }

        float s0 = sv[0] + sv[1], m0 = sv[0] - sv[1];
        float s1 = sv[2] + sv[3], m1 = sv[2] - sv[3];
        float s2 = sv[4] + sv[5], m2 = sv[4] - sv[5];

        float tv[8];
        tv[0] = cx * xc;
        tv[1] = cA[0] * s0;
        tv[2] = cA[1] * s1;
        tv[3] = cA[2] * s2;
        tv[4] = cG[0]*m0 + cG[1]*m1 + cG[2]*m2;
        tv[5] = cG[3]*m0 + cG[4]*m1 + cG[5]*m2;
        tv[6] = cG[6]*m0 + cG[7]*m1 + cG[8]*m2;
        tv[7] = cLs[0]*s0 + cLs[1]*s1 + cLs[2]*s2 + cLx * xc;

        #pragma unroll
        for (int t = 0; t < 8; t++) {
            unsigned long long v2 = pack2(tv[t]);
            const ulonglong2* wrow = (const ulonglong2*)(s_wmixT + (t*CCH + c)*CCH);
            #pragma unroll
            for (int j = 0; j < 8; j++) {
                ulonglong2 q = wrow[j];
                ffma2(acc[2*j+0], q.x, v2);
                ffma2(acc[2*j+1], q.y, v2);
            }
        }
    }

    // ---- Phase 4: out = x + delta + b_mix ----
    float* __restrict__ on = out + (size_t)n * CCH * DHW;
    #pragma unroll
    for (int j = 0; j < 16; j++) {
        float2 dv = unpack2(acc[j]);
        int o0 = 2*j, o1 = 2*j + 1;
        on[o0*DHW + zyx] = xn[o0*DHW + zyx] + dv.x + s_bmix[o0];
        on[o1*DHW + zyx] = xn[o1*DHW + zyx] + dv.y + s_bmix[o1];
    }
}

extern "C" void kernel_launch(void* const* d_in, const int* in_sizes, int n_in,
                              void* d_out, int out_size)
{
    const float* x       = (const float*)d_in[0];
    const float* w_field = (const float*)d_in[1];
    const float* b_field = (const float*)d_in[2];
    const float* gates   = (const float*)d_in[3];
    const float* w_mix   = (const float*)d_in[4];
    const float* b_mix   = (const float*)d_in[5];
    float* out = (float*)d_out;

    int total_vox = in_sizes[0] / CCH;               // N * D * H * W
    int blocks = (total_vox + THREADS - 1) / THREADS; // 864 for N=2
    geo_sample3d_kernel<<<blocks, THREADS>>>(x, w_field, b_field, gates, w_mix, b_mix,
                                             out, total_vox);
}